// round 8
// baseline (speedup 1.0000x reference)
#include <cuda_runtime.h>
#include <math.h>
#include <cstdint>

#define B_    8
#define N_    512
#define KN    128
#define ATOMS 4096
#define DRDIM 1600
#define F0    240
#define NTAB  512
#define SMAXF 1.3335f

// ---------------- scratch ----------------
__device__ float g_DR[ATOMS * DRDIM];
__device__ float g_H1[ATOMS * F0];
__device__ float g_H2[ATOMS * F0];
__device__ float g_H3[ATOMS * F0];
__device__ float g_tab[(NTAB + 1) * 100];
__device__ float g_WT1[F0 * DRDIM];   // fw0^T  [240][1600]
__device__ float g_WT2[F0 * F0];
__device__ float g_WT3[F0 * F0];

__device__ __forceinline__ float tanhfast(float x) {
    float e = __expf(2.0f * x);
    return 1.0f - __fdividef(2.0f, e + 1.0f);
}

__device__ __forceinline__ void split_tf32(float v, float& hi, float& lo) {
    asm("cvt.rna.tf32.f32 %0, %1;" : "=f"(hi) : "f"(v));
    float r = v - hi;
    asm("cvt.rna.tf32.f32 %0, %1;" : "=f"(lo) : "f"(r));
}

// m16n8k8 tf32 mma: D += A*B  (A 16x8 row-major, B 8x8 col-major)
__device__ __forceinline__ void mma8(float* d, const uint32_t* a,
                                     uint32_t b0, uint32_t b1) {
    asm volatile(
        "mma.sync.aligned.m16n8k8.row.col.f32.tf32.tf32.f32 "
        "{%0,%1,%2,%3}, {%4,%5,%6,%7}, {%8,%9}, {%0,%1,%2,%3};"
        : "+f"(d[0]), "+f"(d[1]), "+f"(d[2]), "+f"(d[3])
        : "r"(a[0]), "r"(a[1]), "r"(a[2]), "r"(a[3]), "r"(b0), "r"(b1));
}

// smem float offsets: A[buf][part]: 32x20; B[buf][part]: 240x20; bias 240
#define SOA(buf, part) (((buf) * 2 + (part)) * 640)
#define SOB(buf, part) (2560 + ((buf) * 2 + (part)) * 4800)
#define SOBIAS         21760
#define SM_FLOATS      22000
#define SM_BYTES       (SM_FLOATS * 4)

// ====== tf32 mma.sync GEMM: C[4096,240] = tanh(A[4096,K] @ WT^T + bias) ====
// 128 threads = 4 warps (wm in {0,1}, wn in {0,1}); BM=32, BK=16.
__global__ __launch_bounds__(128) void mma_gemm(
    const float* __restrict__ A, const float* __restrict__ WT,
    const float* __restrict__ bias, float* __restrict__ C, int K)
{
    extern __shared__ float smf[];
    const int tid  = threadIdx.x;
    const int lane = tid & 31;
    const int wid  = tid >> 5;
    const int wm   = wid & 1;         // 16-row slice
    const int wn   = wid >> 1;        // 120-col slice
    const int gid  = lane >> 2;       // 0..7
    const int tig  = lane & 3;        // 0..3
    const int bm   = blockIdx.x * 32;
    const int T    = K / 16;

    // stage bias
    for (int i = tid; i < F0; i += 128) smf[SOBIAS + i] = bias[i];

    float acc[15][4];
#pragma unroll
    for (int f = 0; f < 15; f++)
#pragma unroll
        for (int j = 0; j < 4; j++) acc[f][j] = 0.0f;

    // ---- staging lambdas (LDG into regs, then split+STS) ----
    const int ar = tid >> 2, ac = tid & 3;          // A: 128 float4, 1/thread
    float4 av;
    float4 bv[8];

    auto ldg_tile = [&](int kk0) {
        av = *(const float4*)(A + (size_t)(bm + ar) * K + kk0 + ac * 4);
#pragma unroll
        for (int j = 0; j < 8; j++) {
            int i = tid + j * 128;
            if (i < 960) {
                int n = i >> 2, c = i & 3;
                bv[j] = *(const float4*)(WT + (size_t)n * K + kk0 + c * 4);
            }
        }
    };
    auto sts_tile = [&](int buf) {
        float4 h, l;
        split_tf32(av.x, h.x, l.x); split_tf32(av.y, h.y, l.y);
        split_tf32(av.z, h.z, l.z); split_tf32(av.w, h.w, l.w);
        *(float4*)(smf + SOA(buf, 0) + ar * 20 + ac * 4) = h;
        *(float4*)(smf + SOA(buf, 1) + ar * 20 + ac * 4) = l;
#pragma unroll
        for (int j = 0; j < 8; j++) {
            int i = tid + j * 128;
            if (i < 960) {
                int n = i >> 2, c = i & 3;
                split_tf32(bv[j].x, h.x, l.x); split_tf32(bv[j].y, h.y, l.y);
                split_tf32(bv[j].z, h.z, l.z); split_tf32(bv[j].w, h.w, l.w);
                *(float4*)(smf + SOB(buf, 0) + n * 20 + c * 4) = h;
                *(float4*)(smf + SOB(buf, 1) + n * 20 + c * 4) = l;
            }
        }
    };

    // prologue
    ldg_tile(0);
    sts_tile(0);
    __syncthreads();

    for (int t = 0; t < T; t++) {
        const int buf = t & 1;
        if (t + 1 < T) ldg_tile((t + 1) * 16);

        const float* pAh = smf + SOA(buf, 0);
        const float* pAl = smf + SOA(buf, 1);
        const float* pBh = smf + SOB(buf, 0);
        const float* pBl = smf + SOB(buf, 1);
        const int ra = wm * 16 + gid;
#pragma unroll
        for (int ks = 0; ks < 2; ks++) {
            const int k0 = ks * 8;
            uint32_t ah[4], al[4];
            ah[0] = __float_as_uint(pAh[ ra      * 20 + k0 + tig]);
            ah[1] = __float_as_uint(pAh[(ra + 8) * 20 + k0 + tig]);
            ah[2] = __float_as_uint(pAh[ ra      * 20 + k0 + tig + 4]);
            ah[3] = __float_as_uint(pAh[(ra + 8) * 20 + k0 + tig + 4]);
            al[0] = __float_as_uint(pAl[ ra      * 20 + k0 + tig]);
            al[1] = __float_as_uint(pAl[(ra + 8) * 20 + k0 + tig]);
            al[2] = __float_as_uint(pAl[ ra      * 20 + k0 + tig + 4]);
            al[3] = __float_as_uint(pAl[(ra + 8) * 20 + k0 + tig + 4]);
#pragma unroll
            for (int nf = 0; nf < 15; nf++) {
                const int rb = wn * 120 + nf * 8 + gid;
                uint32_t bh0 = __float_as_uint(pBh[rb * 20 + k0 + tig]);
                uint32_t bh1 = __float_as_uint(pBh[rb * 20 + k0 + tig + 4]);
                uint32_t bl0 = __float_as_uint(pBl[rb * 20 + k0 + tig]);
                uint32_t bl1 = __float_as_uint(pBl[rb * 20 + k0 + tig + 4]);
                mma8(acc[nf], ah, bh0, bh1);
                mma8(acc[nf], ah, bl0, bl1);
                mma8(acc[nf], al, bh0, bh1);
            }
        }
        if (t + 1 < T) sts_tile(1 - buf);
        __syncthreads();
    }

    // epilogue: bias + tanh, direct float2 stores
    const int r0 = bm + wm * 16 + gid;
#pragma unroll
    for (int nf = 0; nf < 15; nf++) {
        const int col = wn * 120 + nf * 8 + tig * 2;
        const float b0 = smf[SOBIAS + col];
        const float b1 = smf[SOBIAS + col + 1];
        float2 v0, v1;
        v0.x = tanhfast(acc[nf][0] + b0);
        v0.y = tanhfast(acc[nf][1] + b1);
        v1.x = tanhfast(acc[nf][2] + b0);
        v1.y = tanhfast(acc[nf][3] + b1);
        *(float2*)(C + (size_t)r0 * F0 + col)       = v0;
        *(float2*)(C + (size_t)(r0 + 8) * F0 + col) = v1;
    }
}

// ---------------- weight transpose: WT[N][K] = W[K][N] ----------------
__global__ __launch_bounds__(256) void transpose_kernel(
    const float* __restrict__ W, float* __restrict__ WT, int K, int N)
{
    __shared__ float t[32][33];
    int k0 = blockIdx.x * 32, n0 = blockIdx.y * 32;
    int x = threadIdx.x, y = threadIdx.y;
#pragma unroll
    for (int dy = 0; dy < 32; dy += 8) {
        int k = k0 + y + dy, n = n0 + x;
        t[y + dy][x] = (k < K && n < N) ? W[(size_t)k * N + n] : 0.0f;
    }
    __syncthreads();
#pragma unroll
    for (int dy = 0; dy < 32; dy += 8) {
        int n = n0 + y + dy, k = k0 + x;
        if (n < N && k < K) WT[(size_t)n * K + k] = t[x][y + dy];
    }
}

// ---------------- kernel 0: build G(S) table ----------------
__global__ __launch_bounds__(128) void build_tab_kernel(
    const float* __restrict__ ew0, const float* __restrict__ eb0,
    const float* __restrict__ ew1, const float* __restrict__ eb1,
    const float* __restrict__ ew2, const float* __restrict__ eb2)
{
    int i = blockIdx.x * 128 + threadIdx.x;
    if (i > NTAB) return;
    float S = (float)i * (SMAXF / (float)NTAB);
    float h1[25];
#pragma unroll
    for (int k = 0; k < 25; k++)
        h1[k] = tanhfast(fmaf(S, __ldg(&ew0[k]), __ldg(&eb0[k])));
    float h2[50];
#pragma unroll
    for (int k = 0; k < 50; k++) h2[k] = __ldg(&eb1[k]);
#pragma unroll
    for (int q = 0; q < 25; q++) {
        float a = h1[q];
#pragma unroll
        for (int k = 0; k < 50; k++) h2[k] = fmaf(a, __ldg(&ew1[q * 50 + k]), h2[k]);
    }
#pragma unroll
    for (int k = 0; k < 50; k++) h2[k] = tanhfast(h2[k]);
#pragma unroll 1
    for (int c = 0; c < 2; c++) {
        float g[50];
#pragma unroll
        for (int k = 0; k < 50; k++) g[k] = __ldg(&eb2[c * 50 + k]);
#pragma unroll 1
        for (int q = 0; q < 50; q++) {
            float a = h2[q];
#pragma unroll
            for (int k = 0; k < 50; k++)
                g[k] = fmaf(a, __ldg(&ew2[q * 100 + c * 50 + k]), g[k]);
        }
#pragma unroll
        for (int k = 0; k < 50; k++) g_tab[i * 100 + c * 50 + k] = tanhfast(g[k]);
    }
}

// ---------------- kernel 1: geometry + table interp + DR ----------------
__global__ __launch_bounds__(128) void embed_kernel(const float4* __restrict__ img)
{
    __shared__ float sRi[128 * 4];
    __shared__ float sG[128 * 21];
    __shared__ float sB[400];

    const int tid = threadIdx.x;
    const int atom = blockIdx.x;

    float4 p = img[atom * KN + tid];
    float R = p.x * p.x + p.y * p.y + p.z * p.z;
    bool mask = p.w > 0.0f;
    float S = 0.0f;
    if (R < 10.0f) {
        if (mask) S = 1.0f / R;
    } else if (R < 25.0f) {
        S = 0.5f * cosf(0.20943951023931953f * (R - 10.0f)) + 0.5f;
    }
    float coef = mask ? S / R : 0.0f;
    sRi[tid * 4 + 0] = S;
    sRi[tid * 4 + 1] = coef * p.x;
    sRi[tid * 4 + 2] = coef * p.y;
    sRi[tid * 4 + 3] = coef * p.z;

    float t = S * ((float)NTAB / SMAXF);
    int idx = (int)t;
    if (idx > NTAB - 1) idx = NTAB - 1;
    float frac = t - (float)idx;
    const float4* r0 = reinterpret_cast<const float4*>(g_tab + idx * 100);
    const float4* r1 = reinterpret_cast<const float4*>(g_tab + (idx + 1) * 100);
    __syncthreads();

#pragma unroll 1
    for (int chunk = 0; chunk < 5; chunk++) {
#pragma unroll
        for (int q = 0; q < 5; q++) {
            float4 a = __ldg(&r0[chunk * 5 + q]);
            float4 b = __ldg(&r1[chunk * 5 + q]);
            sG[tid * 21 + q * 4 + 0] = fmaf(frac, b.x - a.x, a.x);
            sG[tid * 21 + q * 4 + 1] = fmaf(frac, b.y - a.y, a.y);
            sG[tid * 21 + q * 4 + 2] = fmaf(frac, b.z - a.z, a.z);
            sG[tid * 21 + q * 4 + 3] = fmaf(frac, b.w - a.w, a.w);
        }
        __syncthreads();
        if (tid < 80) {
            int f = tid / 20, c = tid - f * 20;
            float a0 = 0.0f;
#pragma unroll 4
            for (int j = 0; j < 128; j++)
                a0 = fmaf(sRi[(j << 2) + f], sG[j * 21 + c], a0);
            sB[f * 100 + chunk * 20 + c] = a0;
        }
        __syncthreads();
    }

#pragma unroll 1
    for (int o = tid; o < DRDIM; o += 128) {
        int m = o / 100, h = o - m * 100;
        float d = sB[m]       * sB[h]
                + sB[100 + m] * sB[100 + h]
                + sB[200 + m] * sB[200 + h]
                + sB[300 + m] * sB[300 + h];
        g_DR[atom * DRDIM + o] = d;
    }
}

// ---------------- Ei ----------------
__global__ __launch_bounds__(256) void ei_kernel(
    const float* __restrict__ H3, const float* __restrict__ fw3,
    const float* __restrict__ fb3, float* __restrict__ out)
{
    int gw = (blockIdx.x * blockDim.x + threadIdx.x) >> 5;
    int lane = threadIdx.x & 31;
    if (gw >= ATOMS) return;
    const float* row = H3 + gw * F0;
    float a = 0.0f;
#pragma unroll
    for (int i = lane; i < F0; i += 32) a = fmaf(row[i], fw3[i], a);
#pragma unroll
    for (int off = 16; off; off >>= 1) a += __shfl_xor_sync(0xFFFFFFFFu, a, off);
    if (lane == 0) out[8 + gw] = a + fb3[0];
}

// ---------------- Etot ----------------
__global__ __launch_bounds__(128) void etot_kernel(float* __restrict__ out)
{
    __shared__ float red[4];
    int b = blockIdx.x;
    int tid = threadIdx.x;
    float a = 0.0f;
    for (int i = tid; i < N_; i += 128) a += out[8 + b * N_ + i];
#pragma unroll
    for (int off = 16; off; off >>= 1) a += __shfl_xor_sync(0xFFFFFFFFu, a, off);
    if ((tid & 31) == 0) red[tid >> 5] = a;
    __syncthreads();
    if (tid == 0) out[b] = red[0] + red[1] + red[2] + red[3];
}

// ---------------- launch ----------------
extern "C" void kernel_launch(void* const* d_in, const int* in_sizes, int n_in,
                              void* d_out, int out_size)
{
    const float* img = (const float*)d_in[0];
    const float* ew0 = (const float*)d_in[1];
    const float* eb0 = (const float*)d_in[2];
    const float* ew1 = (const float*)d_in[3];
    const float* eb1 = (const float*)d_in[4];
    const float* ew2 = (const float*)d_in[5];
    const float* eb2 = (const float*)d_in[6];
    const float* fw0 = (const float*)d_in[7];
    const float* fb0 = (const float*)d_in[8];
    const float* fw1 = (const float*)d_in[9];
    const float* fb1 = (const float*)d_in[10];
    const float* fw2 = (const float*)d_in[11];
    const float* fb2 = (const float*)d_in[12];
    const float* fw3 = (const float*)d_in[13];
    const float* fb3 = (const float*)d_in[14];
    float* out = (float*)d_out;

    void *pDR, *pH1, *pH2, *pH3, *pWT1, *pWT2, *pWT3;
    cudaGetSymbolAddress(&pDR, g_DR);
    cudaGetSymbolAddress(&pH1, g_H1);
    cudaGetSymbolAddress(&pH2, g_H2);
    cudaGetSymbolAddress(&pH3, g_H3);
    cudaGetSymbolAddress(&pWT1, g_WT1);
    cudaGetSymbolAddress(&pWT2, g_WT2);
    cudaGetSymbolAddress(&pWT3, g_WT3);

    cudaFuncSetAttribute(mma_gemm,
                         cudaFuncAttributeMaxDynamicSharedMemorySize, SM_BYTES);

    transpose_kernel<<<dim3(50, 8), dim3(32, 8)>>>(fw0, (float*)pWT1, DRDIM, F0);
    transpose_kernel<<<dim3(8, 8),  dim3(32, 8)>>>(fw1, (float*)pWT2, F0, F0);
    transpose_kernel<<<dim3(8, 8),  dim3(32, 8)>>>(fw2, (float*)pWT3, F0, F0);

    build_tab_kernel<<<(NTAB + 1 + 127) / 128, 128>>>(ew0, eb0, ew1, eb1, ew2, eb2);
    embed_kernel<<<ATOMS, 128>>>((const float4*)img);

    mma_gemm<<<ATOMS / 32, 128, SM_BYTES>>>(
        (const float*)pDR, (const float*)pWT1, fb0, (float*)pH1, DRDIM);
    mma_gemm<<<ATOMS / 32, 128, SM_BYTES>>>(
        (const float*)pH1, (const float*)pWT2, fb1, (float*)pH2, F0);
    mma_gemm<<<ATOMS / 32, 128, SM_BYTES>>>(
        (const float*)pH2, (const float*)pWT3, fb2, (float*)pH3, F0);

    ei_kernel<<<(ATOMS * 32 + 255) / 256, 256>>>((const float*)pH3, fw3, fb3, out);
    etot_kernel<<<B_, 128>>>(out);
}

// round 9
// speedup vs baseline: 1.3085x; 1.3085x over previous
#include <cuda_runtime.h>
#include <math.h>
#include <cstdint>

#define B_    8
#define N_    512
#define KN    128
#define ATOMS 4096
#define DRDIM 1600
#define F0    240
#define NTAB  512
#define SMAXF 1.3335f

// ---------------- scratch ----------------
__device__ float g_B [ATOMS * 400];   // tmpB [atom][f*100+h], 6.5 MB
__device__ float g_H1[ATOMS * F0];
__device__ float g_H2[ATOMS * F0];
__device__ float g_H3[ATOMS * F0];
__device__ float g_tab[(NTAB + 1) * 100];
__device__ float g_WT1[F0 * DRDIM];   // fw0^T  [240][1600]
__device__ float g_WT2[F0 * F0];
__device__ float g_WT3[F0 * F0];

__device__ __forceinline__ float tanhfast(float x) {
    float e = __expf(2.0f * x);
    return 1.0f - __fdividef(2.0f, e + 1.0f);
}

__device__ __forceinline__ void split_tf32(float v, float& hi, float& lo) {
    asm("cvt.rna.tf32.f32 %0, %1;" : "=f"(hi) : "f"(v));
    float r = v - hi;
    asm("cvt.rna.tf32.f32 %0, %1;" : "=f"(lo) : "f"(r));
}

// m16n8k8 tf32 mma: D += A*B
__device__ __forceinline__ void mma8(float* d, const uint32_t* a,
                                     uint32_t b0, uint32_t b1) {
    asm volatile(
        "mma.sync.aligned.m16n8k8.row.col.f32.tf32.tf32.f32 "
        "{%0,%1,%2,%3}, {%4,%5,%6,%7}, {%8,%9}, {%0,%1,%2,%3};"
        : "+f"(d[0]), "+f"(d[1]), "+f"(d[2]), "+f"(d[3])
        : "r"(a[0]), "r"(a[1]), "r"(a[2]), "r"(a[3]), "r"(b0), "r"(b1));
}

// smem float offsets
#define SOA(buf, part) (((buf) * 2 + (part)) * 640)            // 32x20 each
#define SOB(buf, part) (2560 + ((buf) * 2 + (part)) * 4800)    // 240x20 each
#define SOBIAS         21760
#define SOTB           22000                                   // 32 x 404
#define STBS           404
#define SMF_G23        22000
#define SMF_G1         (22000 + 32 * STBS)
#define SMB_G23        (SMF_G23 * 4)
#define SMB_G1         (SMF_G1 * 4)

// ====== tf32 mma.sync GEMM: C[4096,240] = tanh(A @ WT^T + bias) ======
// 192 threads = 6 warps: wm in {0,1} (16-row), wn in {0,1,2} (80-col). BM=32, BK=16.
// FUSED: A synthesized per-tile from tmpB (rank-4 DR), K=1600.
template<bool FUSED>
__global__ __launch_bounds__(192) void mma_gemm(
    const float* __restrict__ A, const float* __restrict__ WT,
    const float* __restrict__ bias, float* __restrict__ C, int K)
{
    extern __shared__ float smf[];
    const int tid  = threadIdx.x;
    const int lane = tid & 31;
    const int wid  = tid >> 5;
    const int wm   = wid & 1;
    const int wn   = wid >> 1;        // 0..2
    const int gid  = lane >> 2;
    const int tig  = lane & 3;
    const int bm   = blockIdx.x * 32;
    const int T    = K / 16;

    for (int i = tid; i < F0; i += 192) smf[SOBIAS + i] = bias[i];

    // FUSED: stage tmpB rows for this CTA's 32 atoms (conflict-free stride 404)
    if (FUSED) {
        for (int i = tid; i < 3200; i += 192) {
            int at = i / 100, q = i - at * 100;
            float4 v = *(const float4*)(A + (size_t)(bm + at) * 400 + q * 4);
            *(float4*)(smf + SOTB + at * STBS + q * 4) = v;
        }
    }

    float acc[10][4];
#pragma unroll
    for (int f = 0; f < 10; f++)
#pragma unroll
        for (int j = 0; j < 4; j++) acc[f][j] = 0.0f;

    const int ar = tid >> 2, ac = tid & 3;     // A: threads 0..127
    float4 av;
    float4 bv[5];

    auto ldg_tile = [&](int kk0) {
        if (!FUSED && tid < 128)
            av = *(const float4*)(A + (size_t)(bm + ar) * K + kk0 + ac * 4);
#pragma unroll
        for (int j = 0; j < 5; j++) {
            int i = tid + j * 192;             // 960 exactly
            int n = i >> 2, c = i & 3;
            bv[j] = *(const float4*)(WT + (size_t)n * K + kk0 + c * 4);
        }
    };
    auto sts_tile = [&](int buf, int kk0) {
        float4 h, l;
        if (tid < 128) {
            if (FUSED) {
                const float* row = smf + SOTB + ar * STBS;
                float vv[4];
#pragma unroll
                for (int j = 0; j < 4; j++) {
                    int c = kk0 + ac * 4 + j;
                    int m = c / 100, hh = c - m * 100;
                    vv[j] = row[m]         * row[hh]
                          + row[100 + m]   * row[100 + hh]
                          + row[200 + m]   * row[200 + hh]
                          + row[300 + m]   * row[300 + hh];
                }
                av = make_float4(vv[0], vv[1], vv[2], vv[3]);
            }
            split_tf32(av.x, h.x, l.x); split_tf32(av.y, h.y, l.y);
            split_tf32(av.z, h.z, l.z); split_tf32(av.w, h.w, l.w);
            *(float4*)(smf + SOA(buf, 0) + ar * 20 + ac * 4) = h;
            *(float4*)(smf + SOA(buf, 1) + ar * 20 + ac * 4) = l;
        }
#pragma unroll
        for (int j = 0; j < 5; j++) {
            int i = tid + j * 192;
            int n = i >> 2, c = i & 3;
            split_tf32(bv[j].x, h.x, l.x); split_tf32(bv[j].y, h.y, l.y);
            split_tf32(bv[j].z, h.z, l.z); split_tf32(bv[j].w, h.w, l.w);
            *(float4*)(smf + SOB(buf, 0) + n * 20 + c * 4) = h;
            *(float4*)(smf + SOB(buf, 1) + n * 20 + c * 4) = l;
        }
    };

    // prologue
    ldg_tile(0);
    if (FUSED) __syncthreads();    // sTB ready before A-gen
    sts_tile(0, 0);
    __syncthreads();

    for (int t = 0; t < T; t++) {
        const int buf = t & 1;
        if (t + 1 < T) ldg_tile((t + 1) * 16);

        const float* pAh = smf + SOA(buf, 0);
        const float* pAl = smf + SOA(buf, 1);
        const float* pBh = smf + SOB(buf, 0);
        const float* pBl = smf + SOB(buf, 1);
        const int ra = wm * 16 + gid;
#pragma unroll
        for (int ks = 0; ks < 2; ks++) {
            const int k0 = ks * 8;
            uint32_t ah[4], al[4];
            ah[0] = __float_as_uint(pAh[ ra      * 20 + k0 + tig]);
            ah[1] = __float_as_uint(pAh[(ra + 8) * 20 + k0 + tig]);
            ah[2] = __float_as_uint(pAh[ ra      * 20 + k0 + tig + 4]);
            ah[3] = __float_as_uint(pAh[(ra + 8) * 20 + k0 + tig + 4]);
            al[0] = __float_as_uint(pAl[ ra      * 20 + k0 + tig]);
            al[1] = __float_as_uint(pAl[(ra + 8) * 20 + k0 + tig]);
            al[2] = __float_as_uint(pAl[ ra      * 20 + k0 + tig + 4]);
            al[3] = __float_as_uint(pAl[(ra + 8) * 20 + k0 + tig + 4]);
#pragma unroll
            for (int nf = 0; nf < 10; nf++) {
                const int rb = wn * 80 + nf * 8 + gid;
                uint32_t bh0 = __float_as_uint(pBh[rb * 20 + k0 + tig]);
                uint32_t bh1 = __float_as_uint(pBh[rb * 20 + k0 + tig + 4]);
                uint32_t bl0 = __float_as_uint(pBl[rb * 20 + k0 + tig]);
                uint32_t bl1 = __float_as_uint(pBl[rb * 20 + k0 + tig + 4]);
                mma8(acc[nf], ah, bh0, bh1);
                mma8(acc[nf], ah, bl0, bl1);
                mma8(acc[nf], al, bh0, bh1);
            }
        }
        if (t + 1 < T) sts_tile(1 - buf, (t + 1) * 16);
        __syncthreads();
    }

    // epilogue: bias + tanh
    const int r0 = bm + wm * 16 + gid;
#pragma unroll
    for (int nf = 0; nf < 10; nf++) {
        const int col = wn * 80 + nf * 8 + tig * 2;
        const float b0 = smf[SOBIAS + col];
        const float b1 = smf[SOBIAS + col + 1];
        float2 v0, v1;
        v0.x = tanhfast(acc[nf][0] + b0);
        v0.y = tanhfast(acc[nf][1] + b1);
        v1.x = tanhfast(acc[nf][2] + b0);
        v1.y = tanhfast(acc[nf][3] + b1);
        *(float2*)(C + (size_t)r0 * F0 + col)       = v0;
        *(float2*)(C + (size_t)(r0 + 8) * F0 + col) = v1;
    }
}

// ---------------- weight transpose: WT[N][K] = W[K][N] ----------------
__global__ __launch_bounds__(256) void transpose_kernel(
    const float* __restrict__ W, float* __restrict__ WT, int K, int N)
{
    __shared__ float t[32][33];
    int k0 = blockIdx.x * 32, n0 = blockIdx.y * 32;
    int x = threadIdx.x, y = threadIdx.y;
#pragma unroll
    for (int dy = 0; dy < 32; dy += 8) {
        int k = k0 + y + dy, n = n0 + x;
        t[y + dy][x] = (k < K && n < N) ? W[(size_t)k * N + n] : 0.0f;
    }
    __syncthreads();
#pragma unroll
    for (int dy = 0; dy < 32; dy += 8) {
        int n = n0 + y + dy, k = k0 + x;
        if (n < N && k < K) WT[(size_t)n * K + k] = t[x][y + dy];
    }
}

// ---------------- kernel 0: build G(S) table, one block per node ----------
__global__ __launch_bounds__(128) void build_tab_kernel(
    const float* __restrict__ ew0, const float* __restrict__ eb0,
    const float* __restrict__ ew1, const float* __restrict__ eb1,
    const float* __restrict__ ew2, const float* __restrict__ eb2)
{
    __shared__ float sw1[25 * 50];
    __shared__ float sw2[50 * 100];
    __shared__ float sh1[25], sh2[50];

    const int tid = threadIdx.x;
    const int i = blockIdx.x;
    const float S = (float)i * (SMAXF / (float)NTAB);

    for (int k = tid; k < 1250; k += 128) sw1[k] = ew1[k];
    for (int k = tid; k < 5000; k += 128) sw2[k] = ew2[k];
    if (tid < 25)
        sh1[tid] = tanhfast(fmaf(S, __ldg(&ew0[tid]), __ldg(&eb0[tid])));
    __syncthreads();

    if (tid < 50) {
        float a = __ldg(&eb1[tid]);
#pragma unroll
        for (int q = 0; q < 25; q++) a = fmaf(sh1[q], sw1[q * 50 + tid], a);
        sh2[tid] = tanhfast(a);
    }
    __syncthreads();

    if (tid < 100) {
        float g = __ldg(&eb2[tid]);
#pragma unroll
        for (int q = 0; q < 50; q++) g = fmaf(sh2[q], sw2[q * 100 + tid], g);
        g_tab[i * 100 + tid] = tanhfast(g);
    }
}

// ---------------- kernel 1: geometry + table interp -> tmpB ----------------
__global__ __launch_bounds__(128) void embed_kernel(const float4* __restrict__ img)
{
    __shared__ float sRi[128 * 4];
    __shared__ float sG[128 * 21];
    __shared__ float sB[400];

    const int tid = threadIdx.x;
    const int atom = blockIdx.x;

    float4 p = img[atom * KN + tid];
    float R = p.x * p.x + p.y * p.y + p.z * p.z;
    bool mask = p.w > 0.0f;
    float S = 0.0f;
    if (R < 10.0f) {
        if (mask) S = 1.0f / R;
    } else if (R < 25.0f) {
        S = 0.5f * cosf(0.20943951023931953f * (R - 10.0f)) + 0.5f;
    }
    float coef = mask ? S / R : 0.0f;
    sRi[tid * 4 + 0] = S;
    sRi[tid * 4 + 1] = coef * p.x;
    sRi[tid * 4 + 2] = coef * p.y;
    sRi[tid * 4 + 3] = coef * p.z;

    float t = S * ((float)NTAB / SMAXF);
    int idx = (int)t;
    if (idx > NTAB - 1) idx = NTAB - 1;
    float frac = t - (float)idx;
    const float4* r0 = reinterpret_cast<const float4*>(g_tab + idx * 100);
    const float4* r1 = reinterpret_cast<const float4*>(g_tab + (idx + 1) * 100);
    __syncthreads();

#pragma unroll 1
    for (int chunk = 0; chunk < 5; chunk++) {
#pragma unroll
        for (int q = 0; q < 5; q++) {
            float4 a = __ldg(&r0[chunk * 5 + q]);
            float4 b = __ldg(&r1[chunk * 5 + q]);
            sG[tid * 21 + q * 4 + 0] = fmaf(frac, b.x - a.x, a.x);
            sG[tid * 21 + q * 4 + 1] = fmaf(frac, b.y - a.y, a.y);
            sG[tid * 21 + q * 4 + 2] = fmaf(frac, b.z - a.z, a.z);
            sG[tid * 21 + q * 4 + 3] = fmaf(frac, b.w - a.w, a.w);
        }
        __syncthreads();
        if (tid < 80) {
            int f = tid / 20, c = tid - f * 20;
            float a0 = 0.0f;
#pragma unroll 4
            for (int j = 0; j < 128; j++)
                a0 = fmaf(sRi[(j << 2) + f], sG[j * 21 + c], a0);
            sB[f * 100 + chunk * 20 + c] = a0;
        }
        __syncthreads();
    }

    // write tmpB only (DR is synthesized inside GEMM1)
    for (int o = tid; o < 400; o += 128)
        g_B[atom * 400 + o] = sB[o];
}

// ---------------- Ei ----------------
__global__ __launch_bounds__(256) void ei_kernel(
    const float* __restrict__ H3, const float* __restrict__ fw3,
    const float* __restrict__ fb3, float* __restrict__ out)
{
    int gw = (blockIdx.x * blockDim.x + threadIdx.x) >> 5;
    int lane = threadIdx.x & 31;
    if (gw >= ATOMS) return;
    const float* row = H3 + gw * F0;
    float a = 0.0f;
#pragma unroll
    for (int i = lane; i < F0; i += 32) a = fmaf(row[i], fw3[i], a);
#pragma unroll
    for (int off = 16; off; off >>= 1) a += __shfl_xor_sync(0xFFFFFFFFu, a, off);
    if (lane == 0) out[8 + gw] = a + fb3[0];
}

// ---------------- Etot ----------------
__global__ __launch_bounds__(128) void etot_kernel(float* __restrict__ out)
{
    __shared__ float red[4];
    int b = blockIdx.x;
    int tid = threadIdx.x;
    float a = 0.0f;
    for (int i = tid; i < N_; i += 128) a += out[8 + b * N_ + i];
#pragma unroll
    for (int off = 16; off; off >>= 1) a += __shfl_xor_sync(0xFFFFFFFFu, a, off);
    if ((tid & 31) == 0) red[tid >> 5] = a;
    __syncthreads();
    if (tid == 0) out[b] = red[0] + red[1] + red[2] + red[3];
}

// ---------------- launch ----------------
extern "C" void kernel_launch(void* const* d_in, const int* in_sizes, int n_in,
                              void* d_out, int out_size)
{
    const float* img = (const float*)d_in[0];
    const float* ew0 = (const float*)d_in[1];
    const float* eb0 = (const float*)d_in[2];
    const float* ew1 = (const float*)d_in[3];
    const float* eb1 = (const float*)d_in[4];
    const float* ew2 = (const float*)d_in[5];
    const float* eb2 = (const float*)d_in[6];
    const float* fw0 = (const float*)d_in[7];
    const float* fb0 = (const float*)d_in[8];
    const float* fw1 = (const float*)d_in[9];
    const float* fb1 = (const float*)d_in[10];
    const float* fw2 = (const float*)d_in[11];
    const float* fb2 = (const float*)d_in[12];
    const float* fw3 = (const float*)d_in[13];
    const float* fb3 = (const float*)d_in[14];
    float* out = (float*)d_out;

    void *pB, *pH1, *pH2, *pH3, *pWT1, *pWT2, *pWT3;
    cudaGetSymbolAddress(&pB,  g_B);
    cudaGetSymbolAddress(&pH1, g_H1);
    cudaGetSymbolAddress(&pH2, g_H2);
    cudaGetSymbolAddress(&pH3, g_H3);
    cudaGetSymbolAddress(&pWT1, g_WT1);
    cudaGetSymbolAddress(&pWT2, g_WT2);
    cudaGetSymbolAddress(&pWT3, g_WT3);

    cudaFuncSetAttribute(mma_gemm<true>,
                         cudaFuncAttributeMaxDynamicSharedMemorySize, SMB_G1);
    cudaFuncSetAttribute(mma_gemm<false>,
                         cudaFuncAttributeMaxDynamicSharedMemorySize, SMB_G23);

    transpose_kernel<<<dim3(50, 8), dim3(32, 8)>>>(fw0, (float*)pWT1, DRDIM, F0);
    transpose_kernel<<<dim3(8, 8),  dim3(32, 8)>>>(fw1, (float*)pWT2, F0, F0);
    transpose_kernel<<<dim3(8, 8),  dim3(32, 8)>>>(fw2, (float*)pWT3, F0, F0);

    build_tab_kernel<<<NTAB + 1, 128>>>(ew0, eb0, ew1, eb1, ew2, eb2);
    embed_kernel<<<ATOMS, 128>>>((const float4*)img);

    // GEMM1: A synthesized from tmpB, K=1600
    mma_gemm<true><<<ATOMS / 32, 192, SMB_G1>>>(
        (const float*)pB, (const float*)pWT1, fb0, (float*)pH1, DRDIM);
    mma_gemm<false><<<ATOMS / 32, 192, SMB_G23>>>(
        (const float*)pH1, (const float*)pWT2, fb1, (float*)pH2, F0);
    mma_gemm<false><<<ATOMS / 32, 192, SMB_G23>>>(
        (const float*)pH2, (const float*)pWT3, fb2, (float*)pH3, F0);

    ei_kernel<<<(ATOMS * 32 + 255) / 256, 256>>>((const float*)pH3, fw3, fb3, out);
    etot_kernel<<<B_, 128>>>(out);
}